// round 4
// baseline (speedup 1.0000x reference)
#include <cuda_runtime.h>
#include <cuda_bf16.h>
#include <mma.h>
#include <cstdint>
#include <cstddef>
#include <type_traits>

using namespace nvcuda;

#define BATCH 8
#define CCH   512
#define NPIX  4096
#define CQD   64

// ---------------- static scratch (no runtime allocation) ----------------
__device__ __nv_bfloat16 g_xb[(size_t)BATCH * CCH * NPIX];
__device__ __nv_bfloat16 g_Wq[CQD * CCH];
__device__ __nv_bfloat16 g_Wk[CQD * CCH];
__device__ __nv_bfloat16 g_Wv[CCH * CCH];
__device__ __nv_bfloat16 g_q[(size_t)BATCH * CQD * NPIX];   // [b,d,i]
__device__ __nv_bfloat16 g_k[(size_t)BATCH * CQD * NPIX];   // [b,d,j]
__device__ __nv_bfloat16 g_v[(size_t)BATCH * CCH * NPIX];   // [b,c,j]
__device__ __nv_bfloat16 g_attn[(size_t)BATCH * NPIX * NPIX]; // exp(scores), unnormalized
__device__ float         g_rowsum[(size_t)BATCH * NPIX];

// ---------------- helpers ----------------
__device__ __forceinline__ uint32_t smem_u32(const void* p) {
    uint32_t a;
    asm("{ .reg .u64 t; cvta.to.shared.u64 t, %1; cvt.u32.u64 %0, t; }" : "=r"(a) : "l"(p));
    return a;
}
__device__ __forceinline__ void cpa16(uint32_t dst, const void* src) {
    asm volatile("cp.async.cg.shared.global [%0], [%1], 16;" :: "r"(dst), "l"(src));
}
#define CP_COMMIT() asm volatile("cp.async.commit_group;" ::: "memory")
#define CP_WAIT(n)  asm volatile("cp.async.wait_group %0;" :: "n"(n) : "memory")

// ---------------- tiny utility kernels ----------------
__global__ void zero_kernel(float* p, int n) {
    int i = blockIdx.x * blockDim.x + threadIdx.x;
    if (i < n) p[i] = 0.0f;
}

__global__ void cast_kernel(const float* __restrict__ in,
                            __nv_bfloat16* __restrict__ out, size_t n4) {
    size_t i = (size_t)blockIdx.x * blockDim.x + threadIdx.x;
    if (i < n4) {
        float4 f = reinterpret_cast<const float4*>(in)[i];
        __nv_bfloat162 a = __floats2bfloat162_rn(f.x, f.y);
        __nv_bfloat162 b = __floats2bfloat162_rn(f.z, f.w);
        uint2 u;
        u.x = *reinterpret_cast<unsigned*>(&a);
        u.y = *reinterpret_cast<unsigned*>(&b);
        reinterpret_cast<uint2*>(out)[i] = u;
    }
}

// ---------------- double-buffered bf16 wmma GEMM ----------------
// C[M,N] = A(MxK) * B(KxN), fp32 accumulate.
// EPI 1: bf16 store (acc + bias[row])
// EPI 2: fp32 store (gamma * acc / rowsum[col] + xres)     (final GEMM)
// EPI 4: bf16 store exp(acc); accumulate row sums          (scores GEMM)
template<int BM, int BN, int BK, int WM, int WN, bool AROW, bool BROW, int EPI>
__global__ void __launch_bounds__((BM / WM) * (BN / WN) * 32)
gemm2(const __nv_bfloat16* __restrict__ A, size_t strideA, int lda,
      const __nv_bfloat16* __restrict__ Bm, size_t strideB, int ldb,
      void* __restrict__ Cm, size_t strideC, int ldc,
      const float* __restrict__ bias,
      const float* __restrict__ gamma,
      const float* __restrict__ xres, size_t strideX,
      float* __restrict__ rowsum,
      int M, int N, int K)
{
    constexpr int WGM = BM / WM, WGN = BN / WN, NW = WGM * WGN;
    constexpr int MI = WM / 16, NI = WN / 16;
    constexpr int SA_R = AROW ? BM : BK, SA_C = AROW ? BK : BM;
    constexpr int SB_R = BROW ? BK : BN, SB_C = BROW ? BN : BK;
    constexpr int LDA_S = SA_C + 8, LDB_S = SB_C + 8;
    constexpr int ABUF = SA_R * LDA_S;   // halves per A buffer
    constexpr int BBUF = SB_R * LDB_S;
    constexpr int ITA = (SA_R * (SA_C / 8)) / (NW * 32);
    constexpr int ITB = (SB_R * (SB_C / 8)) / (NW * 32);
    static_assert((SA_R * (SA_C / 8)) % (NW * 32) == 0, "A div");
    static_assert((SB_R * (SB_C / 8)) % (NW * 32) == 0, "B div");

    extern __shared__ char dsm[];
    __nv_bfloat16* smA = reinterpret_cast<__nv_bfloat16*>(dsm);
    __nv_bfloat16* smB = smA + 2 * ABUF;
    float* stage = reinterpret_cast<float*>(smB + 2 * BBUF);       // [NW][256]
    float* aux = stage + NW * 256;                                 // [<=128]
    const uint32_t smA_u = smem_u32(smA);
    const uint32_t smB_u = smem_u32(smB);

    const int b = blockIdx.z;
    const __nv_bfloat16* Ab = A + strideA * (size_t)b;
    const __nv_bfloat16* Bb = Bm + strideB * (size_t)b;
    const size_t cb = strideC * (size_t)b;

    const int blockM = blockIdx.y * BM;
    const int blockN = blockIdx.x * BN;
    const int tid = threadIdx.x;
    const int wid = tid >> 5, lane = tid & 31;
    const int wm0 = (wid % WGM) * WM;
    const int wn0 = (wid / WGM) * WN;

    if (EPI == 4 && tid < BM) aux[tid] = 0.0f;

    using ALayout = typename std::conditional<AROW, wmma::row_major, wmma::col_major>::type;
    using BLayout = typename std::conditional<BROW, wmma::row_major, wmma::col_major>::type;

    wmma::fragment<wmma::accumulator, 16, 16, 16, float> acc[MI][NI];
#pragma unroll
    for (int i = 0; i < MI; i++)
#pragma unroll
        for (int j = 0; j < NI; j++) wmma::fill_fragment(acc[i][j], 0.0f);

    auto stageA = [&](int buf, int k0) {
#pragma unroll
        for (int it = 0; it < ITA; ++it) {
            int idx = tid + it * NW * 32;
            int r = idx / (SA_C / 8), cv = idx % (SA_C / 8);
            const __nv_bfloat16* src = AROW
                ? Ab + (size_t)(blockM + r) * lda + k0 + cv * 8
                : Ab + (size_t)(k0 + r) * lda + blockM + cv * 8;
            cpa16(smA_u + (uint32_t)(buf * ABUF + r * LDA_S + cv * 8) * 2, src);
        }
    };
    auto stageB = [&](int buf, int k0) {
#pragma unroll
        for (int it = 0; it < ITB; ++it) {
            int idx = tid + it * NW * 32;
            int r = idx / (SB_C / 8), cv = idx % (SB_C / 8);
            const __nv_bfloat16* src = BROW
                ? Bb + (size_t)(k0 + r) * ldb + blockN + cv * 8
                : Bb + (size_t)(blockN + r) * ldb + k0 + cv * 8;
            cpa16(smB_u + (uint32_t)(buf * BBUF + r * LDB_S + cv * 8) * 2, src);
        }
    };

    const int T = K / BK;
    stageA(0, 0); stageB(0, 0); CP_COMMIT();

    for (int t = 0; t < T; ++t) {
        const int cur = t & 1;
        if (t + 1 < T) {
            stageA(cur ^ 1, (t + 1) * BK);
            stageB(cur ^ 1, (t + 1) * BK);
            CP_COMMIT();
            CP_WAIT(1);
        } else {
            CP_WAIT(0);
        }
        __syncthreads();

        const __nv_bfloat16* a0 = smA + cur * ABUF;
        const __nv_bfloat16* b0 = smB + cur * BBUF;
#pragma unroll
        for (int kk = 0; kk < BK; kk += 16) {
            wmma::fragment<wmma::matrix_a, 16, 16, 16, __nv_bfloat16, ALayout> af[MI];
            wmma::fragment<wmma::matrix_b, 16, 16, 16, __nv_bfloat16, BLayout> bfr[NI];
#pragma unroll
            for (int i = 0; i < MI; i++) {
                const __nv_bfloat16* p = AROW ? a0 + (wm0 + i * 16) * LDA_S + kk
                                              : a0 + kk * LDA_S + wm0 + i * 16;
                wmma::load_matrix_sync(af[i], p, LDA_S);
            }
#pragma unroll
            for (int j = 0; j < NI; j++) {
                const __nv_bfloat16* p = BROW ? b0 + kk * LDB_S + wn0 + j * 16
                                              : b0 + (wn0 + j * 16) * LDB_S + kk;
                wmma::load_matrix_sync(bfr[j], p, LDB_S);
            }
#pragma unroll
            for (int i = 0; i < MI; i++)
#pragma unroll
                for (int j = 0; j < NI; j++)
                    wmma::mma_sync(acc[i][j], af[i], bfr[j], acc[i][j]);
        }
        __syncthreads();
    }

    // ---- epilogue ----
    if (EPI == 2) {
        // per-column scale = gamma / rowsum[query col]
        float gval = gamma[0];
        if (tid < BN) aux[tid] = gval / rowsum[(size_t)b * N + blockN + tid];
        __syncthreads();
    }
    if (EPI == 4) __syncthreads();   // aux zero visible

#pragma unroll
    for (int i = 0; i < MI; i++) {
#pragma unroll
        for (int j = 0; j < NI; j++) {
            wmma::store_matrix_sync(&stage[wid * 256], acc[i][j], 16, wmma::mem_row_major);
            __syncwarp();
            int rowBase = blockM + wm0 + i * 16;
            int colBase = blockN + wn0 + j * 16;
            if (EPI == 4) {
                // each lane owns rows r = lane>>1 paired: process 8 elems/lane with
                // per-row register partials, then 1 shared atomic per (lane,row).
                // Layout: e = lane..lane+224 step 32 -> r = e>>4 varies; instead
                // accumulate into a local map of up to 8 rows.
                float pr[8];
                int prow[8];
                int np = 0;
#pragma unroll
                for (int e = lane; e < 256; e += 32) {
                    int r = e >> 4, c = e & 15;
                    float ev = __expf(stage[wid * 256 + e]);
                    size_t o = (size_t)(rowBase + r) * ldc + colBase + c;
                    ((__nv_bfloat16*)Cm)[cb + o] = __float2bfloat16(ev);
                    if (np > 0 && prow[np - 1] == r) {
                        pr[np - 1] += ev;
                    } else {
                        prow[np] = r; pr[np] = ev; ++np;
                    }
                }
#pragma unroll
                for (int u = 0; u < 8; ++u)
                    if (u < np) atomicAdd(&aux[wm0 + i * 16 + prow[u]], pr[u]);
            } else {
#pragma unroll
                for (int e = lane; e < 256; e += 32) {
                    int r = e >> 4, c = e & 15;
                    float val = stage[wid * 256 + e];
                    size_t o = (size_t)(rowBase + r) * ldc + colBase + c;
                    if (EPI == 1) {
                        ((__nv_bfloat16*)Cm)[cb + o] = __float2bfloat16(val + bias[rowBase + r]);
                    } else {  // EPI 2
                        ((float*)Cm)[cb + o] =
                            val * aux[wn0 + j * 16 + c] + xres[strideX * (size_t)b + o];
                    }
                }
            }
            __syncwarp();
        }
    }

    if (EPI == 4) {
        __syncthreads();
        if (tid < BM)
            atomicAdd(&rowsum[(size_t)b * M + blockM + tid], aux[tid]);
    }
}

// host-side smem size mirror
static constexpr size_t gemm_smem(int BM, int BN, int BK, int WM, int WN,
                                  bool AROW, bool BROW) {
    int SA_R = AROW ? BM : BK, SA_C = AROW ? BK : BM;
    int SB_R = BROW ? BK : BN, SB_C = BROW ? BN : BK;
    int NW = (BM / WM) * (BN / WN);
    return (size_t)2 * SA_R * (SA_C + 8) * 2 + (size_t)2 * SB_R * (SB_C + 8) * 2 +
           (size_t)NW * 256 * 4 + 512;
}

// ---------------- launch ----------------
extern "C" void kernel_launch(void* const* d_in, const int* in_sizes, int n_in,
                              void* d_out, int out_size) {
    const float* x     = (const float*)d_in[0];
    const float* Wq    = (const float*)d_in[1];
    const float* bq    = (const float*)d_in[2];
    const float* Wk    = (const float*)d_in[3];
    const float* bk    = (const float*)d_in[4];
    const float* Wv    = (const float*)d_in[5];
    const float* bv    = (const float*)d_in[6];
    const float* gamma = (const float*)d_in[7];

    __nv_bfloat16 *xb, *wq, *wk, *wv, *q, *k, *v, *attn;
    float* rowsum;
    cudaGetSymbolAddress((void**)&xb, g_xb);
    cudaGetSymbolAddress((void**)&wq, g_Wq);
    cudaGetSymbolAddress((void**)&wk, g_Wk);
    cudaGetSymbolAddress((void**)&wv, g_Wv);
    cudaGetSymbolAddress((void**)&q, g_q);
    cudaGetSymbolAddress((void**)&k, g_k);
    cudaGetSymbolAddress((void**)&v, g_v);
    cudaGetSymbolAddress((void**)&attn, g_attn);
    cudaGetSymbolAddress((void**)&rowsum, g_rowsum);

    const size_t sX = (size_t)CCH * NPIX;
    const size_t sQ = (size_t)CQD * NPIX;
    const size_t sS = (size_t)NPIX * NPIX;

    // zero row sums (graph-replay safe: re-zeroed every call)
    zero_kernel<<<(BATCH * NPIX + 255) / 256, 256>>>(rowsum, BATCH * NPIX);

    // casts
    {
        size_t n4 = (size_t)BATCH * sX / 4;
        cast_kernel<<<(unsigned)((n4 + 255) / 256), 256>>>(x, xb, n4);
        size_t nq4 = (size_t)CQD * CCH / 4;
        cast_kernel<<<(unsigned)((nq4 + 255) / 256), 256>>>(Wq, wq, nq4);
        cast_kernel<<<(unsigned)((nq4 + 255) / 256), 256>>>(Wk, wk, nq4);
        size_t nv4 = (size_t)CCH * CCH / 4;
        cast_kernel<<<(unsigned)((nv4 + 255) / 256), 256>>>(Wv, wv, nv4);
    }

    // q = Wq @ xb + bq ; k = Wk @ xb + bk   [64 x 4096] bf16
    {
        auto kfn = gemm2<64, 128, 64, 32, 32, true, true, 1>;
        size_t sm = gemm_smem(64, 128, 64, 32, 32, true, true);
        cudaFuncSetAttribute(kfn, cudaFuncAttributeMaxDynamicSharedMemorySize, (int)sm);
        dim3 g(NPIX / 128, 1, BATCH);
        kfn<<<g, 256, sm>>>(wq, 0, CCH, xb, sX, NPIX, q, sQ, NPIX, bq,
                            nullptr, nullptr, 0, nullptr, CQD, NPIX, CCH);
        kfn<<<g, 256, sm>>>(wk, 0, CCH, xb, sX, NPIX, k, sQ, NPIX, bk,
                            nullptr, nullptr, 0, nullptr, CQD, NPIX, CCH);
    }

    // v = Wv @ xb + bv   [512 x 4096] bf16
    {
        auto kfn = gemm2<128, 128, 64, 64, 32, true, true, 1>;
        size_t sm = gemm_smem(128, 128, 64, 64, 32, true, true);
        cudaFuncSetAttribute(kfn, cudaFuncAttributeMaxDynamicSharedMemorySize, (int)sm);
        dim3 g(NPIX / 128, CCH / 128, BATCH);
        kfn<<<g, 256, sm>>>(wv, 0, CCH, xb, sX, NPIX, v, sX, NPIX, bv,
                            nullptr, nullptr, 0, nullptr, CCH, NPIX, CCH);
    }

    // attn = exp(q^T k) bf16 + rowsum accumulation  [4096 x 4096]
    {
        auto kfn = gemm2<128, 128, 64, 64, 32, false, true, 4>;
        size_t sm = gemm_smem(128, 128, 64, 64, 32, false, true);
        cudaFuncSetAttribute(kfn, cudaFuncAttributeMaxDynamicSharedMemorySize, (int)sm);
        dim3 g(NPIX / 128, NPIX / 128, BATCH);
        kfn<<<g, 256, sm>>>(q, sQ, NPIX, k, sQ, NPIX, attn, sS, NPIX, nullptr,
                            nullptr, nullptr, 0, rowsum, NPIX, NPIX, CQD);
    }

    // out[c,i] = gamma/rowsum[i] * sum_j v[c,j]*attn[i,j] + x[c,i]
    {
        auto kfn = gemm2<128, 128, 64, 64, 32, true, false, 2>;
        size_t sm = gemm_smem(128, 128, 64, 64, 32, true, false);
        cudaFuncSetAttribute(kfn, cudaFuncAttributeMaxDynamicSharedMemorySize, (int)sm);
        dim3 g(NPIX / 128, CCH / 128, BATCH);
        kfn<<<g, 256, sm>>>(v, sX, NPIX, attn, sS, NPIX, d_out, sX, NPIX, nullptr,
                            gamma, x, sX, rowsum, CCH, NPIX, NPIX);
    }
}